// round 15
// baseline (speedup 1.0000x reference)
#include <cuda_runtime.h>
#include <cuda_bf16.h>
#include <math.h>

#define L_TOT 2433
#define LPAD  2496          // 39*64, multiple of 16
#define ROWS_P 2857         // 34*34 + 30*30 + 27*27 + 72-row zero block
#define ZROW  (2785 + 35)   // center of zero block
#define ZSENT 2433          // sentinel l column (always zero in C and a)

// ---------------- static scratch (zero-initialized at module load) ----------------
__device__ __align__(16) float g_ref1[4*512*832];       // scale 0.9, 28x28 (stride 832)
__device__ __align__(16) float g_ref2[4*512*640];       // scale 0.8, 25x25 (stride 640)
__device__ __align__(16) float g_mb2 [4*1156*256];      // match_base, padded 34x34 grid, [row][c]
__device__ __align__(16) float g_m2  [4*ROWS_P*256];    // match feats, padded grids, [row][c]
__device__ __align__(16) float g_bt2 [4*ROWS_P*512];    // assembly feats, padded grids, [row][o]
__device__ __align__(16) float g_msq2[4*ROWS_P];        // per-row sum of m^2
__device__ __align__(16) float g_rnorm[4*LPAD];         // 10/max(norm,1e-4), 0 for pad l
__device__ __align__(16) float g_s   [4ull*1024*LPAD];  // a-tilde [t][l]
__device__ __align__(16) float g_a   [4ull*1156*LPAD];  // C corr map (padded t-grid)
__device__ __align__(16) float g_aw  [4ull*1156*LPAD];  // softmax/4 (padded t-grid)
__device__ int2 g_tab[LPAD];                            // l -> {padded row in l-grids, grid width+2}
__device__ int  g_ntab[9][LPAD];                        // l,d -> neighbor linear l (or ZSENT)

// ---------------- conv job property tables (global job id 0..6) ----------------
__constant__ int cj_insel[7] = {0,0,1,2,0,1,2};
__constant__ int cj_inBS[7]  = {512*1024,512*1024,512*832,512*640,512*1024,512*832,512*640};
__constant__ int cj_pstr[7]  = {1024,1024,832,640,1024,832,640};
__constant__ int cj_pval[7]  = {1024,1024,784,625,1024,784,625};
__constant__ int cj_psb[7]   = {0,0,1156,2056,0,1156,2056};
__constant__ int cj_ws[7]    = {32,32,28,25,32,28,25};
// block decode: match group (jobs 0-3, 4 n-tiles of 64), bt group (jobs 4-6, 4 n-tiles of 128)
__constant__ int cjm_end[3]  = {64,128,180};   // cumulative: 64,128,180,(220)
__constant__ int cjb_end[2]  = {64,116};       // cumulative: 64,116,(156)
#define CONVM_BLOCKS 220
#define CONVB_BLOCKS 156

// ---------------- tables ----------------
__global__ void init_tab_k() {
    int l = blockIdx.x*256 + threadIdx.x;
    if (l >= LPAD) return;
    int2 t;
    int seg, ws, li;
    if (l < 1024)      { seg = 0;    ws = 32; li = l; }
    else if (l < 1808) { seg = 1024; ws = 28; li = l - 1024; }
    else if (l < L_TOT){ seg = 1808; ws = 25; li = l - 1808; }
    else               { seg = -1;   ws = 1;  li = 0; }
    if (seg >= 0) {
        int base = (seg == 0) ? 0 : (seg == 1024) ? 1156 : 2056;
        t.y = ws + 2;
        t.x = base + (li/ws + 1)*(ws + 2) + li%ws + 1;
    } else { t.y = 34; t.x = ZROW; }
    g_tab[l] = t;

    int ly = (seg >= 0) ? li/ws : 0, lx = (seg >= 0) ? li%ws : 0;
    #pragma unroll
    for (int d = 0; d < 9; d++) {
        int du = d/3 - 1, dv = d%3 - 1;
        int n = ZSENT;
        if (seg >= 0) {
            int ny = ly + du, nx = lx + dv;
            if ((unsigned)ny < (unsigned)ws && (unsigned)nx < (unsigned)ws)
                n = seg + ny*ws + nx;
        }
        g_ntab[d][l] = n;
    }
}

// ---------------- cubic resize (jax.image.resize, method='cubic', antialias=False) ----------------
__device__ __forceinline__ float keys_cubic(float x) {
    if (x >= 2.0f) return 0.0f;
    if (x >= 1.0f) return ((-0.5f*x + 2.5f)*x - 4.0f)*x + 2.0f;
    return ((1.5f*x - 2.5f)*x)*x + 1.0f;
}

__global__ void resize_k(const float* __restrict__ in, int oh, int ow, int ppad, int sel) {
    int idx = blockIdx.x*256 + threadIdx.x;
    int total = 4*512*oh*ow;
    if (idx >= total) return;
    int x = idx % ow;
    int r = idx / ow;
    int y = r % oh;
    int bc = r / oh;
    float inv = 32.0f / (float)oh;
    float sfy = ((float)y + 0.5f)*inv - 0.5f;
    float sfx = ((float)x + 0.5f)*inv - 0.5f;
    int ky0 = (int)floorf(sfy) - 1;
    int kx0 = (int)floorf(sfx) - 1;
    float wy[4], wx[4], sy = 0.f, sx = 0.f;
    #pragma unroll
    for (int i = 0; i < 4; i++) {
        int k = ky0 + i;
        float w = (k >= 0 && k < 32) ? keys_cubic(fabsf(sfy - (float)k)) : 0.f;
        wy[i] = w; sy += w;
        k = kx0 + i;
        w = (k >= 0 && k < 32) ? keys_cubic(fabsf(sfx - (float)k)) : 0.f;
        wx[i] = w; sx += w;
    }
    const float* src = in + (size_t)bc*1024;
    float acc = 0.f;
    #pragma unroll
    for (int i = 0; i < 4; i++) {
        int ky = ky0 + i; if (ky < 0 || ky >= 32) continue;
        #pragma unroll
        for (int j = 0; j < 4; j++) {
            int kx = kx0 + j; if (kx < 0 || kx >= 32) continue;
            acc += wy[i]*wx[j]*src[ky*32 + kx];
        }
    }
    float* outp = (sel == 1) ? g_ref1 : g_ref2;
    outp[(size_t)bc*ppad + y*ow + x] = acc / (sy*sx);
}

// ---------------- TF32 / BF16 helpers ----------------
__device__ __forceinline__ unsigned f2tf(float x) {
    unsigned u;
    asm("cvt.rna.tf32.f32 %0, %1;" : "=r"(u) : "f"(x));
    return u;
}
__device__ __forceinline__ void mma_tf(float* c, unsigned a0, unsigned a1, unsigned a2, unsigned a3,
                                       unsigned b0, unsigned b1) {
    asm volatile(
        "mma.sync.aligned.m16n8k8.row.col.f32.tf32.tf32.f32 "
        "{%0,%1,%2,%3},{%4,%5,%6,%7},{%8,%9},{%0,%1,%2,%3};"
        : "+f"(c[0]), "+f"(c[1]), "+f"(c[2]), "+f"(c[3])
        : "r"(a0), "r"(a1), "r"(a2), "r"(a3), "r"(b0), "r"(b1));
}
__device__ __forceinline__ void mma_bf(float* c, unsigned a0, unsigned a1, unsigned a2, unsigned a3,
                                       unsigned b0, unsigned b1) {
    asm volatile(
        "mma.sync.aligned.m16n8k16.row.col.f32.bf16.bf16.f32 "
        "{%0,%1,%2,%3},{%4,%5,%6,%7},{%8,%9},{%0,%1,%2,%3};"
        : "+f"(c[0]), "+f"(c[1]), "+f"(c[2]), "+f"(c[3])
        : "r"(a0), "r"(a1), "r"(a2), "r"(a3), "r"(b0), "r"(b1));
}
// split (x,y) into hi/lo bf16x2 pairs: x in low half (k even), y in high half (k odd)
__device__ __forceinline__ void f2bf2p(float x, float y, unsigned& hi, unsigned& lo) {
    __nv_bfloat162 h = __floats2bfloat162_rn(x, y);
    hi = *reinterpret_cast<unsigned*>(&h);
    float rx = x - __bfloat162float(__low2bfloat16(h));
    float ry = y - __bfloat162float(__high2bfloat16(h));
    __nv_bfloat162 l = __floats2bfloat162_rn(rx, ry);
    lo = *reinterpret_cast<unsigned*>(&l);
}

// ---------------- 3xBF16 conv1x1 + bias + PReLU (match jobs 0-3, fp32-accurate) ----------------
__global__ __launch_bounds__(256) void conv_m_bf3_k(
    const float* __restrict__ xin,
    const float* __restrict__ w0, const float* __restrict__ bi0, const float* __restrict__ al0,
    const float* __restrict__ w1, const float* __restrict__ bi1, const float* __restrict__ al1)
{
    int b = blockIdx.z, bx = blockIdx.x;
    int j = (bx >= cjm_end[0]) + (bx >= cjm_end[1]) + (bx >= cjm_end[2]);
    int li = bx - (j ? cjm_end[j-1] : 0);
    int m0 = (li >> 2) << 6, n0 = (li & 3) << 6;

    int insel = cj_insel[j];
    const float* in = (insel == 1) ? g_ref1 : (insel == 2) ? g_ref2 : xin;
    in += (size_t)b * cj_inBS[j];
    int Pstride = cj_pstr[j], Pvalid = cj_pval[j];
    int ws = cj_ws[j], psBase = cj_psb[j];
    const float* W    = (j == 0) ? w0 : w1;
    const float* bias = (j == 0) ? bi0 : bi1;
    const float* alp  = (j == 0) ? al0 : al1;
    float* out = (j == 0) ? g_mb2 : g_m2;
    int outRows = (j == 0) ? 1156 : ROWS_P;
    out += (size_t)b * outRows * 256;

    __shared__ unsigned Ah[8*72], Al[8*72], Bh[8*72], Bl[8*72];

    int tid = threadIdx.x;
    int wid = tid >> 5, lane = tid & 31;
    int wm = (wid >> 1) << 4, wn = (wid & 1) << 5;
    int tig = lane & 3, g = lane >> 2;

    // A loader: warp = kp row (0..7), lane covers 2 m positions
    int kpA = wid;
    int mA2 = lane << 1;
    unsigned swA = ((kpA >> 1) & 3) << 3;
    const float* aptr0 = in + (size_t)(2*kpA)*Pstride + m0 + mA2;
    const float* aptr1 = aptr0 + Pstride;

    // B loader: float4 along k per thread -> 2 kp pairs
    int nB = tid >> 2, kB = (tid & 3) << 2;
    int kpB = kB >> 1;                         // 0,2,4,6
    unsigned swB = ((kpB >> 1) & 3) << 3;      // same for kpB and kpB+1
    const float* wptr = W + (size_t)(n0 + nB)*512 + kB;

    float c[4][4] = {};

    #pragma unroll 1
    for (int c0 = 0; c0 < 512; c0 += 16) {
        float2 r0 = *(const float2*)aptr0;  aptr0 += (size_t)16*Pstride;
        float2 r1 = *(const float2*)aptr1;  aptr1 += (size_t)16*Pstride;
        float4 w4 = *(const float4*)wptr;   wptr += 16;
        __syncthreads();
        unsigned h, l;
        f2bf2p(r0.x, r1.x, h, l);
        Ah[kpA*72 + ((unsigned)mA2 ^ swA)] = h;       Al[kpA*72 + ((unsigned)mA2 ^ swA)] = l;
        f2bf2p(r0.y, r1.y, h, l);
        Ah[kpA*72 + ((unsigned)(mA2+1) ^ swA)] = h;   Al[kpA*72 + ((unsigned)(mA2+1) ^ swA)] = l;
        f2bf2p(w4.x, w4.y, h, l);
        Bh[kpB*72 + ((unsigned)nB ^ swB)] = h;        Bl[kpB*72 + ((unsigned)nB ^ swB)] = l;
        f2bf2p(w4.z, w4.w, h, l);
        Bh[(kpB+1)*72 + ((unsigned)nB ^ swB)] = h;    Bl[(kpB+1)*72 + ((unsigned)nB ^ swB)] = l;
        __syncthreads();
        unsigned swt  = ((tig >> 1) & 3) << 3;
        unsigned swt4 = (((tig + 4) >> 1) & 3) << 3;
        unsigned ah0 = Ah[tig*72     + ((unsigned)(wm + g)     ^ swt)];
        unsigned ah1 = Ah[tig*72     + ((unsigned)(wm + g + 8) ^ swt)];
        unsigned ah2 = Ah[(tig+4)*72 + ((unsigned)(wm + g)     ^ swt4)];
        unsigned ah3 = Ah[(tig+4)*72 + ((unsigned)(wm + g + 8) ^ swt4)];
        unsigned alo0 = Al[tig*72     + ((unsigned)(wm + g)     ^ swt)];
        unsigned alo1 = Al[tig*72     + ((unsigned)(wm + g + 8) ^ swt)];
        unsigned alo2 = Al[(tig+4)*72 + ((unsigned)(wm + g)     ^ swt4)];
        unsigned alo3 = Al[(tig+4)*72 + ((unsigned)(wm + g + 8) ^ swt4)];
        #pragma unroll
        for (int nf = 0; nf < 4; nf++) {
            unsigned nidx = (unsigned)(wn + (nf << 3) + g);
            unsigned bh0 = Bh[tig*72     + (nidx ^ swt)];
            unsigned bh1 = Bh[(tig+4)*72 + (nidx ^ swt4)];
            unsigned bl0 = Bl[tig*72     + (nidx ^ swt)];
            unsigned bl1 = Bl[(tig+4)*72 + (nidx ^ swt4)];
            mma_bf(c[nf], ah0, ah1, ah2, ah3, bh0, bh1);
            mma_bf(c[nf], ah0, ah1, ah2, ah3, bl0, bl1);
            mma_bf(c[nf], alo0, alo1, alo2, alo3, bh0, bh1);
        }
    }

    float alpha = *alp;
    int posA = m0 + wm + g, posB = posA + 8;
    int rowA = -1, rowB = -1;
    if (posA < Pvalid) rowA = psBase + (posA/ws + 1)*(ws + 2) + posA%ws + 1;
    if (posB < Pvalid) rowB = psBase + (posB/ws + 1)*(ws + 2) + posB%ws + 1;
    #pragma unroll
    for (int nf = 0; nf < 4; nf++) {
        int o = n0 + wn + (nf << 3) + (tig << 1);
        float b0 = bias[o], b1 = bias[o+1];
        if (rowA >= 0) {
            float v0 = c[nf][0] + b0, v1 = c[nf][1] + b1;
            v0 = v0 >= 0.f ? v0 : alpha*v0;
            v1 = v1 >= 0.f ? v1 : alpha*v1;
            *(float2*)(out + (size_t)rowA*256 + o) = make_float2(v0, v1);
        }
        if (rowB >= 0) {
            float v2 = c[nf][2] + b0, v3 = c[nf][3] + b1;
            v2 = v2 >= 0.f ? v2 : alpha*v2;
            v3 = v3 >= 0.f ? v3 : alpha*v3;
            *(float2*)(out + (size_t)rowB*256 + o) = make_float2(v2, v3);
        }
    }
}

// ---------------- TF32 conv1x1 + bias + PReLU, 64x128 tile (bt jobs 4-6) ----------------
__global__ __launch_bounds__(256) void conv_bt_k(
    const float* __restrict__ xin,
    const float* __restrict__ W, const float* __restrict__ bias, const float* __restrict__ alp)
{
    int b = blockIdx.z, bx = blockIdx.x;
    int j = (bx >= cjb_end[0]) + (bx >= cjb_end[1]);
    int li = bx - (j ? cjb_end[j-1] : 0);
    j += 4;
    int m0 = (li >> 2) << 6, n0 = (li & 3) << 7;

    int insel = cj_insel[j];
    const float* in = (insel == 1) ? g_ref1 : (insel == 2) ? g_ref2 : xin;
    in += (size_t)b * cj_inBS[j];
    int Pstride = cj_pstr[j], Pvalid = cj_pval[j];
    int ws = cj_ws[j], psBase = cj_psb[j];
    float* out = g_bt2 + (size_t)b * ROWS_P * 512;

    __shared__ unsigned Ah[16*72], Bh[16*136];

    int tid = threadIdx.x;
    int wid = tid >> 5, lane = tid & 31;
    int wm = (wid >> 1) << 4, wn = (wid & 1) << 6;
    int tig = lane & 3, g = lane >> 2;

    int kA = tid >> 4, mA = (tid & 15) << 2;
    int nB = tid >> 2, kB = (tid & 3) << 2;
    unsigned swB = ((kB >> 2) & 3) << 3;
    const float* aptr  = in + (size_t)kA*Pstride + m0 + mA;
    const float* wptr0 = W + (size_t)(n0 + nB)*512 + kB;
    const float* wptr1 = W + (size_t)(n0 + 64 + nB)*512 + kB;

    float c[8][4] = {};

    #pragma unroll 1
    for (int c0 = 0; c0 < 512; c0 += 16) {
        float4 a4  = *(const float4*)aptr;   aptr += (size_t)16*Pstride;
        float4 w4a = *(const float4*)wptr0;  wptr0 += 16;
        float4 w4b = *(const float4*)wptr1;  wptr1 += 16;
        __syncthreads();
        Ah[kA*72 + mA+0] = f2tf(a4.x);
        Ah[kA*72 + mA+1] = f2tf(a4.y);
        Ah[kA*72 + mA+2] = f2tf(a4.z);
        Ah[kA*72 + mA+3] = f2tf(a4.w);
        Bh[(kB+0)*136 + ((unsigned)nB ^ swB)]        = f2tf(w4a.x);
        Bh[(kB+1)*136 + ((unsigned)nB ^ swB)]        = f2tf(w4a.y);
        Bh[(kB+2)*136 + ((unsigned)nB ^ swB)]        = f2tf(w4a.z);
        Bh[(kB+3)*136 + ((unsigned)nB ^ swB)]        = f2tf(w4a.w);
        Bh[(kB+0)*136 + ((unsigned)(nB+64) ^ swB)]   = f2tf(w4b.x);
        Bh[(kB+1)*136 + ((unsigned)(nB+64) ^ swB)]   = f2tf(w4b.y);
        Bh[(kB+2)*136 + ((unsigned)(nB+64) ^ swB)]   = f2tf(w4b.z);
        Bh[(kB+3)*136 + ((unsigned)(nB+64) ^ swB)]   = f2tf(w4b.w);
        __syncthreads();
        #pragma unroll
        for (int kk = 0; kk < 16; kk += 8) {
            int ka = kk + tig, kb2 = ka + 4;
            unsigned ca = ((ka >> 2) & 3) << 3;
            unsigned cb = ((kb2 >> 2) & 3) << 3;
            unsigned ah0 = Ah[ka*72  + wm + g];
            unsigned ah1 = Ah[ka*72  + wm + g + 8];
            unsigned ah2 = Ah[kb2*72 + wm + g];
            unsigned ah3 = Ah[kb2*72 + wm + g + 8];
            #pragma unroll
            for (int nf = 0; nf < 8; nf++) {
                unsigned nidx = (unsigned)(wn + (nf << 3) + g);
                unsigned bh0 = Bh[ka*136  + (nidx ^ ca)];
                unsigned bh1 = Bh[kb2*136 + (nidx ^ cb)];
                mma_tf(c[nf], ah0, ah1, ah2, ah3, bh0, bh1);
            }
        }
    }

    float alpha = *alp;
    int posA = m0 + wm + g, posB = posA + 8;
    int rowA = -1, rowB = -1;
    if (posA < Pvalid) rowA = psBase + (posA/ws + 1)*(ws + 2) + posA%ws + 1;
    if (posB < Pvalid) rowB = psBase + (posB/ws + 1)*(ws + 2) + posB%ws + 1;
    #pragma unroll
    for (int nf = 0; nf < 8; nf++) {
        int o = n0 + wn + (nf << 3) + (tig << 1);
        float b0 = bias[o], b1 = bias[o+1];
        if (rowA >= 0) {
            float v0 = c[nf][0] + b0, v1 = c[nf][1] + b1;
            v0 = v0 >= 0.f ? v0 : alpha*v0;
            v1 = v1 >= 0.f ? v1 : alpha*v1;
            *(float2*)(out + (size_t)rowA*512 + o) = make_float2(v0, v1);
        }
        if (rowB >= 0) {
            float v2 = c[nf][2] + b0, v3 = c[nf][3] + b1;
            v2 = v2 >= 0.f ? v2 : alpha*v2;
            v3 = v3 >= 0.f ? v3 : alpha*v3;
            *(float2*)(out + (size_t)rowB*512 + o) = make_float2(v2, v3);
        }
    }
}

// ---------------- per-row sum of squares of g_m2 ----------------
__global__ void msq_k() {
    int gw = (blockIdx.x*256 + threadIdx.x) >> 5;
    int lane = threadIdx.x & 31;
    if (gw >= 4*ROWS_P) return;
    const float* r = g_m2 + (size_t)gw*256;
    float s = 0.f;
    #pragma unroll
    for (int i = 0; i < 8; i++) { float v = r[lane + (i << 5)]; s += v*v; }
    #pragma unroll
    for (int o = 16; o; o >>= 1) s += __shfl_xor_sync(0xffffffffu, s, o);
    if (!lane) g_msq2[gw] = s;
}

__global__ void rnorm_k() {
    int idx = blockIdx.x*256 + threadIdx.x;
    if (idx >= 4*LPAD) return;
    int b = idx / LPAD, l = idx - b*LPAD;
    float r = 0.f;
    if (l < L_TOT) {
        int2 t = g_tab[l];
        const float* ms = g_msq2 + b*ROWS_P;
        float s = 0.f;
        #pragma unroll
        for (int du = -1; du <= 1; du++)
            #pragma unroll
            for (int dv = -1; dv <= 1; dv++)
                s += ms[t.x + du*t.y + dv];
        r = 10.0f / fmaxf(sqrtf(s), 1e-4f);
    }
    g_rnorm[idx] = r;
}

// ---------------- corr (3xBF16): C[t][l] = sum_c mb[t][c]*m[l][c] -> g_a padded-t rows ----------------
__global__ __launch_bounds__(256) void corr_bf3_k() {
    int b = blockIdx.z;
    const float* Am = g_mb2 + (size_t)b*1156*256;
    const float* Bm = g_m2  + (size_t)b*ROWS_P*256;
    int m0 = blockIdx.x << 6, n0 = blockIdx.y << 6;

    __shared__ unsigned Ah[8*72], Al[8*72], Bh[8*72], Bl[8*72];

    int tid = threadIdx.x;
    int wid = tid >> 5, lane = tid & 31;
    int wm = (wid >> 1) << 4, wn = (wid & 1) << 5;
    int tig = lane & 3, g = lane >> 2;

    int rA = tid >> 2, kv = (tid & 3) << 2;
    int kp0 = kv >> 1;                          // 0,2,4,6
    unsigned sw = ((kp0 >> 1) & 3) << 3;        // same for kp0, kp0+1
    int ml = m0 + rA;
    int arow = ((ml >> 5) + 1)*34 + (ml & 31) + 1;
    int brow = g_tab[n0 + rA].x;
    const float* ap = Am + (size_t)arow*256 + kv;
    const float* bp = Bm + (size_t)brow*256 + kv;

    float c[4][4] = {};

    #pragma unroll 1
    for (int k0 = 0; k0 < 256; k0 += 16) {
        float4 a4 = *(const float4*)(ap + k0);
        float4 b4 = *(const float4*)(bp + k0);
        __syncthreads();
        unsigned h, l;
        unsigned dst = (unsigned)rA ^ sw;
        f2bf2p(a4.x, a4.y, h, l);  Ah[kp0*72 + dst] = h;      Al[kp0*72 + dst] = l;
        f2bf2p(a4.z, a4.w, h, l);  Ah[(kp0+1)*72 + dst] = h;  Al[(kp0+1)*72 + dst] = l;
        f2bf2p(b4.x, b4.y, h, l);  Bh[kp0*72 + dst] = h;      Bl[kp0*72 + dst] = l;
        f2bf2p(b4.z, b4.w, h, l);  Bh[(kp0+1)*72 + dst] = h;  Bl[(kp0+1)*72 + dst] = l;
        __syncthreads();
        unsigned swt  = ((tig >> 1) & 3) << 3;
        unsigned swt4 = (((tig + 4) >> 1) & 3) << 3;
        unsigned ah0 = Ah[tig*72     + ((unsigned)(wm + g)     ^ swt)];
        unsigned ah1 = Ah[tig*72     + ((unsigned)(wm + g + 8) ^ swt)];
        unsigned ah2 = Ah[(tig+4)*72 + ((unsigned)(wm + g)     ^ swt4)];
        unsigned ah3 = Ah[(tig+4)*72 + ((unsigned)(wm + g + 8) ^ swt4)];
        unsigned alo0 = Al[tig*72     + ((unsigned)(wm + g)     ^ swt)];
        unsigned alo1 = Al[tig*72     + ((unsigned)(wm + g + 8) ^ swt)];
        unsigned alo2 = Al[(tig+4)*72 + ((unsigned)(wm + g)     ^ swt4)];
        unsigned alo3 = Al[(tig+4)*72 + ((unsigned)(wm + g + 8) ^ swt4)];
        #pragma unroll
        for (int nf = 0; nf < 4; nf++) {
            unsigned nidx = (unsigned)(wn + (nf << 3) + g);
            unsigned bh0 = Bh[tig*72     + (nidx ^ swt)];
            unsigned bh1 = Bh[(tig+4)*72 + (nidx ^ swt4)];
            unsigned bl0 = Bl[tig*72     + (nidx ^ swt)];
            unsigned bl1 = Bl[(tig+4)*72 + (nidx ^ swt4)];
            mma_bf(c[nf], ah0, ah1, ah2, ah3, bh0, bh1);
            mma_bf(c[nf], ah0, ah1, ah2, ah3, bl0, bl1);
            mma_bf(c[nf], alo0, alo1, alo2, alo3, bh0, bh1);
        }
    }

    int t0 = m0 + wm + g, t1 = t0 + 8;
    int trowA = ((t0 >> 5) + 1)*34 + (t0 & 31) + 1;
    int trowB = ((t1 >> 5) + 1)*34 + (t1 & 31) + 1;
    float* oA = g_a + ((size_t)b*1156 + trowA)*LPAD;
    float* oB = g_a + ((size_t)b*1156 + trowB)*LPAD;
    #pragma unroll
    for (int nf = 0; nf < 4; nf++) {
        int l0 = n0 + wn + (nf << 3) + (tig << 1);
        *(float2*)(oA + l0) = make_float2(c[nf][0], c[nf][1]);
        *(float2*)(oB + l0) = make_float2(c[nf][2], c[nf][3]);
    }
}

// ---------------- fused: score stencil + rnorm + softmax + /4 -> g_aw padded t-grid ----------------
__global__ __launch_bounds__(256) void softmax_f_k() {
    int b = blockIdx.y, t = blockIdx.x;
    int trow = ((t >> 5) + 1)*34 + (t & 31) + 1;
    const float* Cb = g_a + ((size_t)b*1156 + trow)*LPAD;
    const float* rn = g_rnorm + b*LPAD;
    float* orow = g_aw + ((size_t)b*1156 + trow)*LPAD;
    int tid = threadIdx.x;
    const int dt[9] = {-35,-34,-33,-1,0,1,33,34,35};

    float vals[10];
    float mx = -1e30f;
    #pragma unroll
    for (int k = 0; k < 10; k++) {
        int l = tid + (k << 8);
        float v = -1e30f;
        if (l < L_TOT) {
            float s = 0.f;
            #pragma unroll
            for (int d = 0; d < 9; d++)
                s += Cb[(ptrdiff_t)dt[d]*LPAD + g_ntab[d][l]];
            v = s * rn[l];
        }
        vals[k] = v; mx = fmaxf(mx, v);
    }
    __shared__ float red[8], red2[8];
    #pragma unroll
    for (int o = 16; o; o >>= 1) mx = fmaxf(mx, __shfl_xor_sync(0xffffffffu, mx, o));
    if (!(tid & 31)) red[tid >> 5] = mx;
    __syncthreads();
    mx = red[0];
    #pragma unroll
    for (int w = 1; w < 8; w++) mx = fmaxf(mx, red[w]);

    float s = 0.f;
    #pragma unroll
    for (int k = 0; k < 10; k++) {
        int l = tid + (k << 8);
        if (l < L_TOT) { float e = expf(vals[k] - mx); vals[k] = e; s += e; }
    }
    #pragma unroll
    for (int o = 16; o; o >>= 1) s += __shfl_xor_sync(0xffffffffu, s, o);
    if (!(tid & 31)) red2[tid >> 5] = s;
    __syncthreads();
    s = red2[0];
    #pragma unroll
    for (int w = 1; w < 8; w++) s += red2[w];
    float rinv = 0.25f / s;
    #pragma unroll
    for (int k = 0; k < 10; k++) {
        int l = tid + (k << 8);
        if (l < LPAD) orow[l] = (l < L_TOT) ? vals[k]*rinv : 0.f;
    }
}

// ---------------- diagonal stencil over a -> a-tilde (g_s, plain [t][LPAD]) ----------------
__global__ __launch_bounds__(256) void sten_agg_k() {
    int idx = blockIdx.x*256 + threadIdx.x;
    if (idx >= 4*1024*LPAD) return;
    int l = idx % LPAD;
    int r = idx / LPAD;
    int t = r & 1023, b = r >> 10;
    int trow = ((t >> 5) + 1)*34 + (t & 31) + 1;
    const float* Ab = g_aw + ((size_t)b*1156 + trow)*LPAD;
    float s = 0.f;
    #pragma unroll
    for (int d = 0; d < 9; d++) {
        int dt = (d/3 - 1)*34 + (d%3 - 1);
        s += Ab[(ptrdiff_t)dt*LPAD + g_ntab[d][l]];
    }
    g_s[(size_t)idx] = s;
}

// ---------------- assembly GEMM (TF32 mma, 64x128 tile) ----------------
__global__ __launch_bounds__(256) void asm2_tf_k(const float* __restrict__ inp, float* __restrict__ out) {
    int b = blockIdx.z;
    const float* Am = g_s   + (size_t)b*1024*LPAD;    // a-tilde [t][l]
    const float* Bm = g_bt2 + (size_t)b*ROWS_P*512;   // base [row][o]
    int m0 = blockIdx.x << 6, n0 = blockIdx.y << 7;

    __shared__ unsigned As[16*72];
    __shared__ unsigned Bs[16*136];

    int tid = threadIdx.x;
    int wid = tid >> 5, lane = tid & 31;
    int wm = (wid >> 1) << 4;
    int wn = (wid & 1) << 6;
    int tig = lane & 3, g = lane >> 2;

    int rA = tid >> 2, kvA = (tid & 3) << 2;
    int kB = tid >> 4, nv = (tid & 15) << 3;
    const float* ap = Am + (size_t)(m0 + rA)*LPAD + kvA;
    unsigned swA = ((kvA >> 2) & 3) << 3;
    unsigned swB = ((kB >> 2) & 3) << 3;

    float c[8][4] = {};

    #pragma unroll 1
    for (int k0 = 0; k0 < LPAD; k0 += 16) {
        float4 a4 = *(const float4*)(ap + k0);
        int brow = g_tab[k0 + kB].x;
        const float* bsrc = Bm + (size_t)brow*512 + n0 + nv;
        float4 b4a = *(const float4*)bsrc;
        float4 b4b = *(const float4*)(bsrc + 4);
        __syncthreads();
        As[(kvA+0)*72 + ((unsigned)rA ^ swA)] = f2tf(a4.x);
        As[(kvA+1)*72 + ((unsigned)rA ^ swA)] = f2tf(a4.y);
        As[(kvA+2)*72 + ((unsigned)rA ^ swA)] = f2tf(a4.z);
        As[(kvA+3)*72 + ((unsigned)rA ^ swA)] = f2tf(a4.w);
        Bs[kB*136 + ((unsigned)(nv+0) ^ swB)] = f2tf(b4a.x);
        Bs[kB*136 + ((unsigned)(nv+1) ^ swB)] = f2tf(b4a.y);
        Bs[kB*136 + ((unsigned)(nv+2) ^ swB)] = f2tf(b4a.z);
        Bs[kB*136 + ((unsigned)(nv+3) ^ swB)] = f2tf(b4a.w);
        Bs[kB*136 + ((unsigned)(nv+4) ^ swB)] = f2tf(b4b.x);
        Bs[kB*136 + ((unsigned)(nv+5) ^ swB)] = f2tf(b4b.y);
        Bs[kB*136 + ((unsigned)(nv+6) ^ swB)] = f2tf(b4b.z);
        Bs[kB*136 + ((unsigned)(nv+7) ^ swB)] = f2tf(b4b.w);
        __syncthreads();
        #pragma unroll
        for (int kk = 0; kk < 16; kk += 8) {
            int ka = kk + tig, kb2 = kk + tig + 4;
            unsigned ca = ((ka >> 2) & 3) << 3;
            unsigned cb = ((kb2 >> 2) & 3) << 3;
            unsigned a0 = As[ka*72  + ((unsigned)(wm + g)     ^ ca)];
            unsigned a1 = As[ka*72  + ((unsigned)(wm + g + 8) ^ ca)];
            unsigned a2 = As[kb2*72 + ((unsigned)(wm + g)     ^ cb)];
            unsigned a3 = As[kb2*72 + ((unsigned)(wm + g + 8) ^ cb)];
            #pragma unroll
            for (int nf = 0; nf < 8; nf++) {
                unsigned nidx = (unsigned)(wn + (nf << 3) + g);
                unsigned b0 = Bs[ka*136  + (nidx ^ ca)];
                unsigned b1 = Bs[kb2*136 + (nidx ^ cb)];
                mma_tf(c[nf], a0, a1, a2, a3, b0, b1);
            }
        }
    }

    int t0 = m0 + wm + g;
    #pragma unroll
    for (int nf = 0; nf < 8; nf++) {
        int o = n0 + wn + (nf << 3) + (tig << 1);
        size_t base0 = ((size_t)(b*512 + o))*1024;
        out[base0 + t0]            = c[nf][0] + inp[base0 + t0];
        out[base0 + 1024 + t0]     = c[nf][1] + inp[base0 + 1024 + t0];
        out[base0 + t0 + 8]        = c[nf][2] + inp[base0 + t0 + 8];
        out[base0 + 1024 + t0 + 8] = c[nf][3] + inp[base0 + 1024 + t0 + 8];
    }
}

// ---------------- host ----------------
extern "C" void kernel_launch(void* const* d_in, const int* in_sizes, int n_in,
                              void* d_out, int out_size) {
    (void)in_sizes; (void)n_in; (void)out_size;
    const float* input   = (const float*)d_in[0];
    const float* w_base  = (const float*)d_in[1];
    const float* b_base  = (const float*)d_in[2];
    const float* a_base  = (const float*)d_in[3];
    const float* w_match = (const float*)d_in[4];
    const float* b_match = (const float*)d_in[5];
    const float* a_match = (const float*)d_in[6];
    const float* w_asm   = (const float*)d_in[7];
    const float* b_asm   = (const float*)d_in[8];
    const float* a_asm   = (const float*)d_in[9];
    float* out = (float*)d_out;

    init_tab_k<<<(LPAD + 255)/256, 256>>>();
    resize_k<<<(4*512*28*28 + 255)/256, 256>>>(input, 28, 28, 832, 1);
    resize_k<<<(4*512*25*25 + 255)/256, 256>>>(input, 25, 25, 640, 2);

    conv_m_bf3_k<<<dim3(CONVM_BLOCKS, 1, 4), 256>>>(
        input, w_base, b_base, a_base, w_match, b_match, a_match);
    conv_bt_k<<<dim3(CONVB_BLOCKS, 1, 4), 256>>>(
        input, w_asm, b_asm, a_asm);

    msq_k<<<(4*ROWS_P*32 + 255)/256, 256>>>();
    rnorm_k<<<(4*LPAD + 255)/256, 256>>>();

    corr_bf3_k<<<dim3(16, LPAD/64, 4), 256>>>();
    softmax_f_k<<<dim3(1024, 4), 256>>>();
    sten_agg_k<<<(4*1024*LPAD)/256, 256>>>();
    asm2_tf_k<<<dim3(16, 4, 4), 256>>>(input, out);
}

// round 16
// speedup vs baseline: 1.0803x; 1.0803x over previous
#include <cuda_runtime.h>
#include <cuda_bf16.h>
#include <cuda_fp16.h>
#include <math.h>

#define L_TOT 2433
#define LPAD  2496          // 39*64, multiple of 16
#define ROWS_P 2857         // 34*34 + 30*30 + 27*27 + 72-row zero block
#define ZROW  (2785 + 35)   // center of zero block
#define ZSENT 2433          // sentinel l column (always zero in C and a)

// ---------------- static scratch (zero-initialized at module load) ----------------
__device__ __align__(16) float g_ref1[4*512*832];       // scale 0.9, 28x28 (stride 832)
__device__ __align__(16) float g_ref2[4*512*640];       // scale 0.8, 25x25 (stride 640)
__device__ __align__(16) float g_mb2 [4*1156*256];      // match_base, padded 34x34 grid, [row][c]
__device__ __align__(16) float g_m2  [4*ROWS_P*256];    // match feats, padded grids, [row][c]
__device__ __align__(16) float g_bt2 [4*ROWS_P*512];    // assembly feats, padded grids, [row][o]
__device__ __align__(16) float g_msq2[4*ROWS_P];        // per-row sum of m^2
__device__ __align__(16) float g_rnorm[4*LPAD];         // 10/max(norm,1e-4), 0 for pad l
__device__ __align__(16) __half g_s [4ull*1024*LPAD];   // a-tilde [t][l] (fp16)
__device__ __align__(16) float g_a  [4ull*1156*LPAD];   // C corr map (padded t-grid)
__device__ __align__(16) __half g_aw[4ull*1156*LPAD];   // softmax/4 (padded t-grid, fp16)
__device__ int2 g_tab[LPAD];                            // l -> {padded row in l-grids, grid width+2}
__device__ int  g_ntab[9][LPAD];                        // l,d -> neighbor linear l (or ZSENT)

// ---------------- conv job property tables (global job id 0..6) ----------------
__constant__ int cj_insel[7] = {0,0,1,2,0,1,2};
__constant__ int cj_inBS[7]  = {512*1024,512*1024,512*832,512*640,512*1024,512*832,512*640};
__constant__ int cj_pstr[7]  = {1024,1024,832,640,1024,832,640};
__constant__ int cj_pval[7]  = {1024,1024,784,625,1024,784,625};
__constant__ int cj_psb[7]   = {0,0,1156,2056,0,1156,2056};
__constant__ int cj_ws[7]    = {32,32,28,25,32,28,25};
// block decode: match group (jobs 0-3, 4 n-tiles), bt group (jobs 4-6, 8 n-tiles)
__constant__ int cjm_end[3]  = {64,128,180};   // cumulative: 64,128,180,(220)
__constant__ int cjb_end[2]  = {128,232};      // cumulative: 128,232,(312)
#define CONVM_BLOCKS 220
#define CONVB_BLOCKS 312

// ---------------- tables ----------------
__global__ void init_tab_k() {
    int l = blockIdx.x*256 + threadIdx.x;
    if (l >= LPAD) return;
    int2 t;
    int seg, ws, li;
    if (l < 1024)      { seg = 0;    ws = 32; li = l; }
    else if (l < 1808) { seg = 1024; ws = 28; li = l - 1024; }
    else if (l < L_TOT){ seg = 1808; ws = 25; li = l - 1808; }
    else               { seg = -1;   ws = 1;  li = 0; }
    if (seg >= 0) {
        int base = (seg == 0) ? 0 : (seg == 1024) ? 1156 : 2056;
        t.y = ws + 2;
        t.x = base + (li/ws + 1)*(ws + 2) + li%ws + 1;
    } else { t.y = 34; t.x = ZROW; }
    g_tab[l] = t;

    int ly = (seg >= 0) ? li/ws : 0, lx = (seg >= 0) ? li%ws : 0;
    #pragma unroll
    for (int d = 0; d < 9; d++) {
        int du = d/3 - 1, dv = d%3 - 1;
        int n = ZSENT;
        if (seg >= 0) {
            int ny = ly + du, nx = lx + dv;
            if ((unsigned)ny < (unsigned)ws && (unsigned)nx < (unsigned)ws)
                n = seg + ny*ws + nx;
        }
        g_ntab[d][l] = n;
    }
}

// ---------------- cubic resize (jax.image.resize, method='cubic', antialias=False) ----------------
__device__ __forceinline__ float keys_cubic(float x) {
    if (x >= 2.0f) return 0.0f;
    if (x >= 1.0f) return ((-0.5f*x + 2.5f)*x - 4.0f)*x + 2.0f;
    return ((1.5f*x - 2.5f)*x)*x + 1.0f;
}

__global__ void resize_k(const float* __restrict__ in, int oh, int ow, int ppad, int sel) {
    int idx = blockIdx.x*256 + threadIdx.x;
    int total = 4*512*oh*ow;
    if (idx >= total) return;
    int x = idx % ow;
    int r = idx / ow;
    int y = r % oh;
    int bc = r / oh;
    float inv = 32.0f / (float)oh;
    float sfy = ((float)y + 0.5f)*inv - 0.5f;
    float sfx = ((float)x + 0.5f)*inv - 0.5f;
    int ky0 = (int)floorf(sfy) - 1;
    int kx0 = (int)floorf(sfx) - 1;
    float wy[4], wx[4], sy = 0.f, sx = 0.f;
    #pragma unroll
    for (int i = 0; i < 4; i++) {
        int k = ky0 + i;
        float w = (k >= 0 && k < 32) ? keys_cubic(fabsf(sfy - (float)k)) : 0.f;
        wy[i] = w; sy += w;
        k = kx0 + i;
        w = (k >= 0 && k < 32) ? keys_cubic(fabsf(sfx - (float)k)) : 0.f;
        wx[i] = w; sx += w;
    }
    const float* src = in + (size_t)bc*1024;
    float acc = 0.f;
    #pragma unroll
    for (int i = 0; i < 4; i++) {
        int ky = ky0 + i; if (ky < 0 || ky >= 32) continue;
        #pragma unroll
        for (int j = 0; j < 4; j++) {
            int kx = kx0 + j; if (kx < 0 || kx >= 32) continue;
            acc += wy[i]*wx[j]*src[ky*32 + kx];
        }
    }
    float* outp = (sel == 1) ? g_ref1 : g_ref2;
    outp[(size_t)bc*ppad + y*ow + x] = acc / (sy*sx);
}

// ---------------- TF32 / BF16 helpers ----------------
__device__ __forceinline__ unsigned f2tf(float x) {
    unsigned u;
    asm("cvt.rna.tf32.f32 %0, %1;" : "=r"(u) : "f"(x));
    return u;
}
__device__ __forceinline__ void mma_tf(float* c, unsigned a0, unsigned a1, unsigned a2, unsigned a3,
                                       unsigned b0, unsigned b1) {
    asm volatile(
        "mma.sync.aligned.m16n8k8.row.col.f32.tf32.tf32.f32 "
        "{%0,%1,%2,%3},{%4,%5,%6,%7},{%8,%9},{%0,%1,%2,%3};"
        : "+f"(c[0]), "+f"(c[1]), "+f"(c[2]), "+f"(c[3])
        : "r"(a0), "r"(a1), "r"(a2), "r"(a3), "r"(b0), "r"(b1));
}
__device__ __forceinline__ void mma_bf(float* c, unsigned a0, unsigned a1, unsigned a2, unsigned a3,
                                       unsigned b0, unsigned b1) {
    asm volatile(
        "mma.sync.aligned.m16n8k16.row.col.f32.bf16.bf16.f32 "
        "{%0,%1,%2,%3},{%4,%5,%6,%7},{%8,%9},{%0,%1,%2,%3};"
        : "+f"(c[0]), "+f"(c[1]), "+f"(c[2]), "+f"(c[3])
        : "r"(a0), "r"(a1), "r"(a2), "r"(a3), "r"(b0), "r"(b1));
}
// split (x,y) into hi/lo bf16x2 pairs: x in low half (k even), y in high half (k odd)
__device__ __forceinline__ void f2bf2p(float x, float y, unsigned& hi, unsigned& lo) {
    __nv_bfloat162 h = __floats2bfloat162_rn(x, y);
    hi = *reinterpret_cast<unsigned*>(&h);
    float rx = x - __bfloat162float(__low2bfloat16(h));
    float ry = y - __bfloat162float(__high2bfloat16(h));
    __nv_bfloat162 l = __floats2bfloat162_rn(rx, ry);
    lo = *reinterpret_cast<unsigned*>(&l);
}

// ---------------- 3xBF16 conv1x1 + bias + PReLU (match jobs 0-3, fp32-accurate) ----------------
__global__ __launch_bounds__(256) void conv_m_bf3_k(
    const float* __restrict__ xin,
    const float* __restrict__ w0, const float* __restrict__ bi0, const float* __restrict__ al0,
    const float* __restrict__ w1, const float* __restrict__ bi1, const float* __restrict__ al1)
{
    int b = blockIdx.z, bx = blockIdx.x;
    int j = (bx >= cjm_end[0]) + (bx >= cjm_end[1]) + (bx >= cjm_end[2]);
    int li = bx - (j ? cjm_end[j-1] : 0);
    int m0 = (li >> 2) << 6, n0 = (li & 3) << 6;

    int insel = cj_insel[j];
    const float* in = (insel == 1) ? g_ref1 : (insel == 2) ? g_ref2 : xin;
    in += (size_t)b * cj_inBS[j];
    int Pstride = cj_pstr[j], Pvalid = cj_pval[j];
    int ws = cj_ws[j], psBase = cj_psb[j];
    const float* W    = (j == 0) ? w0 : w1;
    const float* bias = (j == 0) ? bi0 : bi1;
    const float* alp  = (j == 0) ? al0 : al1;
    float* out = (j == 0) ? g_mb2 : g_m2;
    int outRows = (j == 0) ? 1156 : ROWS_P;
    out += (size_t)b * outRows * 256;

    __shared__ unsigned Ah[8*72], Al[8*72], Bh[8*72], Bl[8*72];

    int tid = threadIdx.x;
    int wid = tid >> 5, lane = tid & 31;
    int wm = (wid >> 1) << 4, wn = (wid & 1) << 5;
    int tig = lane & 3, g = lane >> 2;

    int kpA = wid;
    int mA2 = lane << 1;
    unsigned swA = ((kpA >> 1) & 3) << 3;
    const float* aptr0 = in + (size_t)(2*kpA)*Pstride + m0 + mA2;
    const float* aptr1 = aptr0 + Pstride;

    int nB = tid >> 2, kB = (tid & 3) << 2;
    int kpB = kB >> 1;
    unsigned swB = ((kpB >> 1) & 3) << 3;
    const float* wptr = W + (size_t)(n0 + nB)*512 + kB;

    float c[4][4] = {};

    #pragma unroll 1
    for (int c0 = 0; c0 < 512; c0 += 16) {
        float2 r0 = *(const float2*)aptr0;  aptr0 += (size_t)16*Pstride;
        float2 r1 = *(const float2*)aptr1;  aptr1 += (size_t)16*Pstride;
        float4 w4 = *(const float4*)wptr;   wptr += 16;
        __syncthreads();
        unsigned h, l;
        f2bf2p(r0.x, r1.x, h, l);
        Ah[kpA*72 + ((unsigned)mA2 ^ swA)] = h;       Al[kpA*72 + ((unsigned)mA2 ^ swA)] = l;
        f2bf2p(r0.y, r1.y, h, l);
        Ah[kpA*72 + ((unsigned)(mA2+1) ^ swA)] = h;   Al[kpA*72 + ((unsigned)(mA2+1) ^ swA)] = l;
        f2bf2p(w4.x, w4.y, h, l);
        Bh[kpB*72 + ((unsigned)nB ^ swB)] = h;        Bl[kpB*72 + ((unsigned)nB ^ swB)] = l;
        f2bf2p(w4.z, w4.w, h, l);
        Bh[(kpB+1)*72 + ((unsigned)nB ^ swB)] = h;    Bl[(kpB+1)*72 + ((unsigned)nB ^ swB)] = l;
        __syncthreads();
        unsigned swt  = ((tig >> 1) & 3) << 3;
        unsigned swt4 = (((tig + 4) >> 1) & 3) << 3;
        unsigned ah0 = Ah[tig*72     + ((unsigned)(wm + g)     ^ swt)];
        unsigned ah1 = Ah[tig*72     + ((unsigned)(wm + g + 8) ^ swt)];
        unsigned ah2 = Ah[(tig+4)*72 + ((unsigned)(wm + g)     ^ swt4)];
        unsigned ah3 = Ah[(tig+4)*72 + ((unsigned)(wm + g + 8) ^ swt4)];
        unsigned alo0 = Al[tig*72     + ((unsigned)(wm + g)     ^ swt)];
        unsigned alo1 = Al[tig*72     + ((unsigned)(wm + g + 8) ^ swt)];
        unsigned alo2 = Al[(tig+4)*72 + ((unsigned)(wm + g)     ^ swt4)];
        unsigned alo3 = Al[(tig+4)*72 + ((unsigned)(wm + g + 8) ^ swt4)];
        #pragma unroll
        for (int nf = 0; nf < 4; nf++) {
            unsigned nidx = (unsigned)(wn + (nf << 3) + g);
            unsigned bh0 = Bh[tig*72     + (nidx ^ swt)];
            unsigned bh1 = Bh[(tig+4)*72 + (nidx ^ swt4)];
            unsigned bl0 = Bl[tig*72     + (nidx ^ swt)];
            unsigned bl1 = Bl[(tig+4)*72 + (nidx ^ swt4)];
            mma_bf(c[nf], ah0, ah1, ah2, ah3, bh0, bh1);
            mma_bf(c[nf], ah0, ah1, ah2, ah3, bl0, bl1);
            mma_bf(c[nf], alo0, alo1, alo2, alo3, bh0, bh1);
        }
    }

    float alpha = *alp;
    int posA = m0 + wm + g, posB = posA + 8;
    int rowA = -1, rowB = -1;
    if (posA < Pvalid) rowA = psBase + (posA/ws + 1)*(ws + 2) + posA%ws + 1;
    if (posB < Pvalid) rowB = psBase + (posB/ws + 1)*(ws + 2) + posB%ws + 1;
    #pragma unroll
    for (int nf = 0; nf < 4; nf++) {
        int o = n0 + wn + (nf << 3) + (tig << 1);
        float b0 = bias[o], b1 = bias[o+1];
        if (rowA >= 0) {
            float v0 = c[nf][0] + b0, v1 = c[nf][1] + b1;
            v0 = v0 >= 0.f ? v0 : alpha*v0;
            v1 = v1 >= 0.f ? v1 : alpha*v1;
            *(float2*)(out + (size_t)rowA*256 + o) = make_float2(v0, v1);
        }
        if (rowB >= 0) {
            float v2 = c[nf][2] + b0, v3 = c[nf][3] + b1;
            v2 = v2 >= 0.f ? v2 : alpha*v2;
            v3 = v3 >= 0.f ? v3 : alpha*v3;
            *(float2*)(out + (size_t)rowB*256 + o) = make_float2(v2, v3);
        }
    }
}

// ---------------- TF32 conv1x1 + bias + PReLU (bt jobs 4-6, 64x64 tile) ----------------
__global__ __launch_bounds__(256) void conv_bt_k(
    const float* __restrict__ xin,
    const float* __restrict__ W, const float* __restrict__ bias, const float* __restrict__ alp)
{
    int b = blockIdx.z, bx = blockIdx.x;
    int j = (bx >= cjb_end[0]) + (bx >= cjb_end[1]);
    int li = bx - (j ? cjb_end[j-1] : 0);
    j += 4;
    int m0 = (li >> 3) << 6, n0 = (li & 7) << 6;

    int insel = cj_insel[j];
    const float* in = (insel == 1) ? g_ref1 : (insel == 2) ? g_ref2 : xin;
    in += (size_t)b * cj_inBS[j];
    int Pstride = cj_pstr[j], Pvalid = cj_pval[j];
    int ws = cj_ws[j], psBase = cj_psb[j];
    float* out = g_bt2 + (size_t)b * ROWS_P * 512;

    __shared__ unsigned Ah[16*72], Bh[16*72];

    int tid = threadIdx.x;
    int wid = tid >> 5, lane = tid & 31;
    int wm = (wid >> 1) << 4, wn = (wid & 1) << 5;
    int tig = lane & 3, g = lane >> 2;

    int kA = tid >> 4, mA = (tid & 15) << 2;
    int nB = tid >> 2, kB = (tid & 3) << 2;
    unsigned swB = ((kB >> 2) & 3) << 3;
    const float* aptr = in + (size_t)kA*Pstride + m0 + mA;
    const float* wptr = W + (size_t)(n0 + nB)*512 + kB;

    float c[4][4] = {};

    #pragma unroll 1
    for (int c0 = 0; c0 < 512; c0 += 16) {
        float4 a4 = *(const float4*)aptr;  aptr += (size_t)16*Pstride;
        float4 w4 = *(const float4*)wptr;  wptr += 16;
        __syncthreads();
        Ah[kA*72 + mA+0] = f2tf(a4.x);
        Ah[kA*72 + mA+1] = f2tf(a4.y);
        Ah[kA*72 + mA+2] = f2tf(a4.z);
        Ah[kA*72 + mA+3] = f2tf(a4.w);
        Bh[(kB+0)*72 + (nB ^ swB)] = f2tf(w4.x);
        Bh[(kB+1)*72 + (nB ^ swB)] = f2tf(w4.y);
        Bh[(kB+2)*72 + (nB ^ swB)] = f2tf(w4.z);
        Bh[(kB+3)*72 + (nB ^ swB)] = f2tf(w4.w);
        __syncthreads();
        #pragma unroll
        for (int kk = 0; kk < 16; kk += 8) {
            int ka = kk + tig, kb2 = ka + 4;
            unsigned ca = ((ka >> 2) & 3) << 3;
            unsigned cb = ((kb2 >> 2) & 3) << 3;
            unsigned ah0 = Ah[ka*72  + wm + g];
            unsigned ah1 = Ah[ka*72  + wm + g + 8];
            unsigned ah2 = Ah[kb2*72 + wm + g];
            unsigned ah3 = Ah[kb2*72 + wm + g + 8];
            #pragma unroll
            for (int nf = 0; nf < 4; nf++) {
                unsigned nidx = (unsigned)(wn + (nf << 3) + g);
                unsigned bh0 = Bh[ka*72  + (nidx ^ ca)];
                unsigned bh1 = Bh[kb2*72 + (nidx ^ cb)];
                mma_tf(c[nf], ah0, ah1, ah2, ah3, bh0, bh1);
            }
        }
    }

    float alpha = *alp;
    int posA = m0 + wm + g, posB = posA + 8;
    int rowA = -1, rowB = -1;
    if (posA < Pvalid) rowA = psBase + (posA/ws + 1)*(ws + 2) + posA%ws + 1;
    if (posB < Pvalid) rowB = psBase + (posB/ws + 1)*(ws + 2) + posB%ws + 1;
    #pragma unroll
    for (int nf = 0; nf < 4; nf++) {
        int o = n0 + wn + (nf << 3) + (tig << 1);
        float b0 = bias[o], b1 = bias[o+1];
        if (rowA >= 0) {
            float v0 = c[nf][0] + b0, v1 = c[nf][1] + b1;
            v0 = v0 >= 0.f ? v0 : alpha*v0;
            v1 = v1 >= 0.f ? v1 : alpha*v1;
            *(float2*)(out + (size_t)rowA*512 + o) = make_float2(v0, v1);
        }
        if (rowB >= 0) {
            float v2 = c[nf][2] + b0, v3 = c[nf][3] + b1;
            v2 = v2 >= 0.f ? v2 : alpha*v2;
            v3 = v3 >= 0.f ? v3 : alpha*v3;
            *(float2*)(out + (size_t)rowB*512 + o) = make_float2(v2, v3);
        }
    }
}

// ---------------- per-row sum of squares of g_m2 ----------------
__global__ void msq_k() {
    int gw = (blockIdx.x*256 + threadIdx.x) >> 5;
    int lane = threadIdx.x & 31;
    if (gw >= 4*ROWS_P) return;
    const float* r = g_m2 + (size_t)gw*256;
    float s = 0.f;
    #pragma unroll
    for (int i = 0; i < 8; i++) { float v = r[lane + (i << 5)]; s += v*v; }
    #pragma unroll
    for (int o = 16; o; o >>= 1) s += __shfl_xor_sync(0xffffffffu, s, o);
    if (!lane) g_msq2[gw] = s;
}

__global__ void rnorm_k() {
    int idx = blockIdx.x*256 + threadIdx.x;
    if (idx >= 4*LPAD) return;
    int b = idx / LPAD, l = idx - b*LPAD;
    float r = 0.f;
    if (l < L_TOT) {
        int2 t = g_tab[l];
        const float* ms = g_msq2 + b*ROWS_P;
        float s = 0.f;
        #pragma unroll
        for (int du = -1; du <= 1; du++)
            #pragma unroll
            for (int dv = -1; dv <= 1; dv++)
                s += ms[t.x + du*t.y + dv];
        r = 10.0f / fmaxf(sqrtf(s), 1e-4f);
    }
    g_rnorm[idx] = r;
}

// ---------------- corr (3xBF16): C[t][l] = sum_c mb[t][c]*m[l][c] -> g_a padded-t rows ----------------
__global__ __launch_bounds__(256) void corr_bf3_k() {
    int b = blockIdx.z;
    const float* Am = g_mb2 + (size_t)b*1156*256;
    const float* Bm = g_m2  + (size_t)b*ROWS_P*256;
    int m0 = blockIdx.x << 6, n0 = blockIdx.y << 6;

    __shared__ unsigned Ah[8*72], Al[8*72], Bh[8*72], Bl[8*72];

    int tid = threadIdx.x;
    int wid = tid >> 5, lane = tid & 31;
    int wm = (wid >> 1) << 4, wn = (wid & 1) << 5;
    int tig = lane & 3, g = lane >> 2;

    int rA = tid >> 2, kv = (tid & 3) << 2;
    int kp0 = kv >> 1;
    unsigned sw = ((kp0 >> 1) & 3) << 3;
    int ml = m0 + rA;
    int arow = ((ml >> 5) + 1)*34 + (ml & 31) + 1;
    int brow = g_tab[n0 + rA].x;
    const float* ap = Am + (size_t)arow*256 + kv;
    const float* bp = Bm + (size_t)brow*256 + kv;

    float c[4][4] = {};

    #pragma unroll 1
    for (int k0 = 0; k0 < 256; k0 += 16) {
        float4 a4 = *(const float4*)(ap + k0);
        float4 b4 = *(const float4*)(bp + k0);
        __syncthreads();
        unsigned h, l;
        unsigned dst = (unsigned)rA ^ sw;
        f2bf2p(a4.x, a4.y, h, l);  Ah[kp0*72 + dst] = h;      Al[kp0*72 + dst] = l;
        f2bf2p(a4.z, a4.w, h, l);  Ah[(kp0+1)*72 + dst] = h;  Al[(kp0+1)*72 + dst] = l;
        f2bf2p(b4.x, b4.y, h, l);  Bh[kp0*72 + dst] = h;      Bl[kp0*72 + dst] = l;
        f2bf2p(b4.z, b4.w, h, l);  Bh[(kp0+1)*72 + dst] = h;  Bl[(kp0+1)*72 + dst] = l;
        __syncthreads();
        unsigned swt  = ((tig >> 1) & 3) << 3;
        unsigned swt4 = (((tig + 4) >> 1) & 3) << 3;
        unsigned ah0 = Ah[tig*72     + ((unsigned)(wm + g)     ^ swt)];
        unsigned ah1 = Ah[tig*72     + ((unsigned)(wm + g + 8) ^ swt)];
        unsigned ah2 = Ah[(tig+4)*72 + ((unsigned)(wm + g)     ^ swt4)];
        unsigned ah3 = Ah[(tig+4)*72 + ((unsigned)(wm + g + 8) ^ swt4)];
        unsigned alo0 = Al[tig*72     + ((unsigned)(wm + g)     ^ swt)];
        unsigned alo1 = Al[tig*72     + ((unsigned)(wm + g + 8) ^ swt)];
        unsigned alo2 = Al[(tig+4)*72 + ((unsigned)(wm + g)     ^ swt4)];
        unsigned alo3 = Al[(tig+4)*72 + ((unsigned)(wm + g + 8) ^ swt4)];
        #pragma unroll
        for (int nf = 0; nf < 4; nf++) {
            unsigned nidx = (unsigned)(wn + (nf << 3) + g);
            unsigned bh0 = Bh[tig*72     + (nidx ^ swt)];
            unsigned bh1 = Bh[(tig+4)*72 + (nidx ^ swt4)];
            unsigned bl0 = Bl[tig*72     + (nidx ^ swt)];
            unsigned bl1 = Bl[(tig+4)*72 + (nidx ^ swt4)];
            mma_bf(c[nf], ah0, ah1, ah2, ah3, bh0, bh1);
            mma_bf(c[nf], ah0, ah1, ah2, ah3, bl0, bl1);
            mma_bf(c[nf], alo0, alo1, alo2, alo3, bh0, bh1);
        }
    }

    int t0 = m0 + wm + g, t1 = t0 + 8;
    int trowA = ((t0 >> 5) + 1)*34 + (t0 & 31) + 1;
    int trowB = ((t1 >> 5) + 1)*34 + (t1 & 31) + 1;
    float* oA = g_a + ((size_t)b*1156 + trowA)*LPAD;
    float* oB = g_a + ((size_t)b*1156 + trowB)*LPAD;
    #pragma unroll
    for (int nf = 0; nf < 4; nf++) {
        int l0 = n0 + wn + (nf << 3) + (tig << 1);
        *(float2*)(oA + l0) = make_float2(c[nf][0], c[nf][1]);
        *(float2*)(oB + l0) = make_float2(c[nf][2], c[nf][3]);
    }
}

// ---------------- fused: score stencil + rnorm + softmax + /4 -> g_aw (fp16) ----------------
__global__ __launch_bounds__(256) void softmax_f_k() {
    int b = blockIdx.y, t = blockIdx.x;
    int trow = ((t >> 5) + 1)*34 + (t & 31) + 1;
    const float* Cb = g_a + ((size_t)b*1156 + trow)*LPAD;
    const float* rn = g_rnorm + b*LPAD;
    __half* orow = g_aw + ((size_t)b*1156 + trow)*LPAD;
    int tid = threadIdx.x;
    const int dt[9] = {-35,-34,-33,-1,0,1,33,34,35};

    float vals[10];
    float mx = -1e30f;
    #pragma unroll
    for (int k = 0; k < 10; k++) {
        int l = tid + (k << 8);
        float v = -1e30f;
        if (l < L_TOT) {
            float s = 0.f;
            #pragma unroll
            for (int d = 0; d < 9; d++)
                s += Cb[(ptrdiff_t)dt[d]*LPAD + g_ntab[d][l]];
            v = s * rn[l];
        }
        vals[k] = v; mx = fmaxf(mx, v);
    }
    __shared__ float red[8], red2[8];
    #pragma unroll
    for (int o = 16; o; o >>= 1) mx = fmaxf(mx, __shfl_xor_sync(0xffffffffu, mx, o));
    if (!(tid & 31)) red[tid >> 5] = mx;
    __syncthreads();
    mx = red[0];
    #pragma unroll
    for (int w = 1; w < 8; w++) mx = fmaxf(mx, red[w]);

    float s = 0.f;
    #pragma unroll
    for (int k = 0; k < 10; k++) {
        int l = tid + (k << 8);
        if (l < L_TOT) { float e = expf(vals[k] - mx); vals[k] = e; s += e; }
    }
    #pragma unroll
    for (int o = 16; o; o >>= 1) s += __shfl_xor_sync(0xffffffffu, s, o);
    if (!(tid & 31)) red2[tid >> 5] = s;
    __syncthreads();
    s = red2[0];
    #pragma unroll
    for (int w = 1; w < 8; w++) s += red2[w];
    float rinv = 0.25f / s;
    #pragma unroll
    for (int k = 0; k < 10; k++) {
        int l = tid + (k << 8);
        if (l < LPAD)
            orow[l] = (l < L_TOT) ? __float2half_rn(vals[k]*rinv) : __half(0.f);
    }
}

// ---------------- diagonal stencil over a (fp16) -> a-tilde (g_s, fp16 [t][LPAD]) ----------------
__global__ __launch_bounds__(256) void sten_agg_k() {
    int idx = blockIdx.x*256 + threadIdx.x;
    if (idx >= 4*1024*LPAD) return;
    int l = idx % LPAD;
    int r = idx / LPAD;
    int t = r & 1023, b = r >> 10;
    int trow = ((t >> 5) + 1)*34 + (t & 31) + 1;
    const __half* Ab = g_aw + ((size_t)b*1156 + trow)*LPAD;
    float s = 0.f;
    #pragma unroll
    for (int d = 0; d < 9; d++) {
        int dt = (d/3 - 1)*34 + (d%3 - 1);
        s += __half2float(Ab[(ptrdiff_t)dt*LPAD + g_ntab[d][l]]);
    }
    g_s[(size_t)idx] = __float2half_rn(s);
}

// ---------------- assembly GEMM (TF32 mma, 64x64 tile; A from fp16) ----------------
__global__ __launch_bounds__(256) void asm2_tf_k(const float* __restrict__ inp, float* __restrict__ out) {
    int b = blockIdx.z;
    const __half* Am = g_s + (size_t)b*1024*LPAD;     // a-tilde [t][l] fp16
    const float* Bm = g_bt2 + (size_t)b*ROWS_P*512;   // base [row][o]
    int m0 = blockIdx.x << 6, n0 = blockIdx.y << 6;

    __shared__ unsigned As[16*72];
    __shared__ unsigned Bs[16*72];

    int tid = threadIdx.x;
    int wid = tid >> 5, lane = tid & 31;
    int wm = (wid >> 1) << 4;
    int wn = (wid & 1) << 5;
    int tig = lane & 3, g = lane >> 2;

    int rA = tid >> 2, kvA = (tid & 3) << 2;
    int kB = tid >> 4, nv = (tid & 15) << 2;
    const __half* ap = Am + (size_t)(m0 + rA)*LPAD + kvA;
    unsigned swA = ((kvA >> 2) & 3) << 3;
    unsigned swB = ((kB >> 2) & 3) << 3;

    float c[4][4] = {};

    #pragma unroll 1
    for (int k0 = 0; k0 < LPAD; k0 += 16) {
        uint2 araw = *(const uint2*)(ap + k0);
        float2 a01 = __half22float2(*reinterpret_cast<__half2*>(&araw.x));
        float2 a23 = __half22float2(*reinterpret_cast<__half2*>(&araw.y));
        int brow = g_tab[k0 + kB].x;
        float4 b4 = *(const float4*)(Bm + (size_t)brow*512 + n0 + nv);
        __syncthreads();
        As[(kvA+0)*72 + ((unsigned)rA ^ swA)] = f2tf(a01.x);
        As[(kvA+1)*72 + ((unsigned)rA ^ swA)] = f2tf(a01.y);
        As[(kvA+2)*72 + ((unsigned)rA ^ swA)] = f2tf(a23.x);
        As[(kvA+3)*72 + ((unsigned)rA ^ swA)] = f2tf(a23.y);
        Bs[kB*72 + ((unsigned)(nv+0) ^ swB)] = f2tf(b4.x);
        Bs[kB*72 + ((unsigned)(nv+1) ^ swB)] = f2tf(b4.y);
        Bs[kB*72 + ((unsigned)(nv+2) ^ swB)] = f2tf(b4.z);
        Bs[kB*72 + ((unsigned)(nv+3) ^ swB)] = f2tf(b4.w);
        __syncthreads();
        #pragma unroll
        for (int kk = 0; kk < 16; kk += 8) {
            int ka = kk + tig, kb2 = kk + tig + 4;
            unsigned ca = ((ka >> 2) & 3) << 3;
            unsigned cb = ((kb2 >> 2) & 3) << 3;
            unsigned a0 = As[ka*72  + ((unsigned)(wm + g)     ^ ca)];
            unsigned a1 = As[ka*72  + ((unsigned)(wm + g + 8) ^ ca)];
            unsigned a2 = As[kb2*72 + ((unsigned)(wm + g)     ^ cb)];
            unsigned a3 = As[kb2*72 + ((unsigned)(wm + g + 8) ^ cb)];
            #pragma unroll
            for (int nf = 0; nf < 4; nf++) {
                unsigned b0 = Bs[ka*72  + ((unsigned)(wn + (nf<<3) + g) ^ ca)];
                unsigned b1 = Bs[kb2*72 + ((unsigned)(wn + (nf<<3) + g) ^ cb)];
                mma_tf(c[nf], a0, a1, a2, a3, b0, b1);
            }
        }
    }

    int t0 = m0 + wm + g;
    #pragma unroll
    for (int nf = 0; nf < 4; nf++) {
        int o = n0 + wn + (nf << 3) + (tig << 1);
        size_t base0 = ((size_t)(b*512 + o))*1024;
        out[base0 + t0]            = c[nf][0] + inp[base0 + t0];
        out[base0 + 1024 + t0]     = c[nf][1] + inp[base0 + 1024 + t0];
        out[base0 + t0 + 8]        = c[nf][2] + inp[base0 + t0 + 8];
        out[base0 + 1024 + t0 + 8] = c[nf][3] + inp[base0 + 1024 + t0 + 8];
    }
}

// ---------------- host ----------------
extern "C" void kernel_launch(void* const* d_in, const int* in_sizes, int n_in,
                              void* d_out, int out_size) {
    (void)in_sizes; (void)n_in; (void)out_size;
    const float* input   = (const float*)d_in[0];
    const float* w_base  = (const float*)d_in[1];
    const float* b_base  = (const float*)d_in[2];
    const float* a_base  = (const float*)d_in[3];
    const float* w_match = (const float*)d_in[4];
    const float* b_match = (const float*)d_in[5];
    const float* a_match = (const float*)d_in[6];
    const float* w_asm   = (const float*)d_in[7];
    const float* b_asm   = (const float*)d_in[8];
    const float* a_asm   = (const float*)d_in[9];
    float* out = (float*)d_out;

    init_tab_k<<<(LPAD + 255)/256, 256>>>();
    resize_k<<<(4*512*28*28 + 255)/256, 256>>>(input, 28, 28, 832, 1);
    resize_k<<<(4*512*25*25 + 255)/256, 256>>>(input, 25, 25, 640, 2);

    conv_m_bf3_k<<<dim3(CONVM_BLOCKS, 1, 4), 256>>>(
        input, w_base, b_base, a_base, w_match, b_match, a_match);
    conv_bt_k<<<dim3(CONVB_BLOCKS, 1, 4), 256>>>(
        input, w_asm, b_asm, a_asm);

    msq_k<<<(4*ROWS_P*32 + 255)/256, 256>>>();
    rnorm_k<<<(4*LPAD + 255)/256, 256>>>();

    corr_bf3_k<<<dim3(16, LPAD/64, 4), 256>>>();
    softmax_f_k<<<dim3(1024, 4), 256>>>();
    sten_agg_k<<<(4*1024*LPAD)/256, 256>>>();
    asm2_tf_k<<<dim3(16, 8, 4), 256>>>(input, out);
}